// round 13
// baseline (speedup 1.0000x reference)
#include <cuda_runtime.h>
#include <math.h>
#include <stdint.h>

#define BB 128
#define SS 200
#define QQ 20000
#define VV 128
#define KK 128
#define CC 64
#define SUMD 128
#define NROWS (BB*SS)

// Sliced per-(b,slice,s) record: [negE(32) | A(32) | W(64)] = 128 floats = 512B
#define NSLICE 4
#define SLICEV 32
#define RECF 128
#define RECB (RECF*4)
#define SCAN_SMEM (SS*RECB)          // 102,400 B

// precompute geometry: CTA = 64 rows x 320 cols, 320 threads, tile 8r x 8c
#define PROWS 64
#define PT 320
#define KCH 16
#define NKCH (KK/KCH)                // 8
#define WCH_E (KCH*VV*4)             // 8192 B
#define WCH_K (KCH*CC*4)             // 4096 B
#define WCH_TOT (2*WCH_E + WCH_K)
// dyn smem float offsets (A stored DUPLICATED as float2 pairs)
#define OFF_QK   (PROWS*KK*2)        // 16384
#define OFF_WE   (2*PROWS*KK*2)      // 32768
#define OFF_WA   (OFF_WE + 2*KCH*VV) // 36864
#define OFF_WK   (OFF_WA + 2*KCH*VV) // 40960
#define OFF_MB   (OFF_WK + 2*KCH*CC) // 43008
#define PRE_SMEM ((OFF_MB + 4)*4)    // ~172 KB

__device__ float g_slice[(size_t)BB * NSLICE * SS * RECF];   // 52.4 MB
__device__ float g_mem[(size_t)BB * VV * CC];                // 4 MB

typedef unsigned long long ull;

__device__ __forceinline__ ull fma2(ull a, ull b, ull c) {
    ull d;
    asm("fma.rn.f32x2 %0, %1, %2, %3;" : "=l"(d) : "l"(a), "l"(b), "l"(c));
    return d;
}
__device__ __forceinline__ ull pack2(float x, float y) {
    ull d;
    asm("mov.b64 %0, {%1, %2};" : "=l"(d) : "f"(x), "f"(y));
    return d;
}
__device__ __forceinline__ float2 unpack2(ull v) {
    float2 r;
    asm("mov.b64 {%0, %1}, %2;" : "=f"(r.x), "=f"(r.y) : "l"(v));
    return r;
}
__device__ __forceinline__ uint32_t smem_u32(const void* p) {
    uint32_t a;
    asm("{ .reg .u64 t; cvta.to.shared.u64 t, %1; cvt.u32.u64 %0, t; }" : "=r"(a) : "l"(p));
    return a;
}
__device__ __forceinline__ void mbar_init(uint32_t mbar, uint32_t cnt) {
    asm volatile("mbarrier.init.shared.b64 [%0], %1;" :: "r"(mbar), "r"(cnt) : "memory");
}
__device__ __forceinline__ void mbar_expect_tx(uint32_t mbar, uint32_t bytes) {
    asm volatile("mbarrier.arrive.expect_tx.shared.b64 _, [%0], %1;" :: "r"(mbar), "r"(bytes) : "memory");
}
__device__ __forceinline__ void mbar_wait(uint32_t mbar, uint32_t parity) {
    asm volatile(
        "{\n\t.reg .pred P;\n"
        "WAITLOOP_%=:\n\t"
        "mbarrier.try_wait.parity.acquire.cta.shared::cta.b64 P, [%0], %1, 0x989680;\n\t"
        "@P bra.uni WAITDONE_%=;\n\t"
        "bra.uni WAITLOOP_%=;\n"
        "WAITDONE_%=:\n\t}"
        :: "r"(mbar), "r"(parity) : "memory");
}
__device__ __forceinline__ void bulk_g2s(uint32_t dst, const void* src, uint32_t bytes, uint32_t mbar) {
    asm volatile(
        "cp.async.bulk.shared::cta.global.mbarrier::complete_tx::bytes [%0], [%1], %2, [%3];"
        :: "r"(dst), "l"(src), "r"(bytes), "r"(mbar) : "memory");
}

// ---------------------------------------------------------------------------
// Kernel A v4: precompute GEMM. 320 threads, thread tile 8 rows x 8 cols.
// A stored duplicated in smem ((a,a) float2) -> LDS.128 yields ready f32x2
// multiplicands for 2 k's; W pairs load packed. Inner loop: LDS+FMA2 only.
// tc = t%40: tc<16 erase cols 8tc; tc<32 add; tc<40 key. tr = t/40: 8 rows.
// ---------------------------------------------------------------------------
__global__ __launch_bounds__(PT) void precompute_kernel(
    const float* __restrict__ q_emb,
    const float* __restrict__ i_emb,
    const float* __restrict__ key_memory,
    const float* __restrict__ erase_W,
    const float* __restrict__ erase_b,
    const float* __restrict__ add_W,
    const float* __restrict__ add_b,
    const int*   __restrict__ input)
{
    extern __shared__ __align__(16) float psm[];
    float2* sIVd = (float2*)psm;                 // [64 rows][128 k] dup pairs
    float2* sQKd = (float2*)(psm + OFF_QK);
    float*  sWE  = psm + OFF_WE;                 // [2][KCH][128]
    float*  sWA  = psm + OFF_WA;
    float*  sWK  = psm + OFF_WK;                 // [2][KCH][64]
    const uint32_t mb = smem_u32(psm + OFF_MB);

    __shared__ float sLg[PROWS][68];
    __shared__ int   sIdx[PROWS];

    const int t    = threadIdx.x;
    const int lane = t & 31;
    const int wid  = t >> 5;
    const int tc   = t % 40;
    const int tr   = t / 40;
    const int row0 = blockIdx.x * PROWS;

    if (t < PROWS) sIdx[t] = input[row0 + t];
    if (t == 0) {
        mbar_init(mb, 1);
        asm volatile("fence.proxy.async.shared::cta;" ::: "memory");
        mbar_expect_tx(mb, WCH_TOT);
        bulk_g2s(smem_u32(sWE), erase_W,    WCH_E, mb);
        bulk_g2s(smem_u32(sWA), add_W,      WCH_E, mb);
        bulk_g2s(smem_u32(sWK), key_memory, WCH_K, mb);
    }
    __syncthreads();

    // Gather embeddings, duplicated: sIVd[r][k] = (v,v)
    for (int r = wid; r < PROWS; r += PT/32) {
        const int idx = sIdx[r];
        const int qid = idx > QQ ? idx - QQ : idx;
        float4 v  = *((const float4*)(i_emb + (size_t)idx * VV) + lane);
        float4 qv = *((const float4*)(q_emb + (size_t)qid * KK) + lane);
        float2* dI = sIVd + r * KK + lane * 4;
        float2* dQ = sQKd + r * KK + lane * 4;
        dI[0] = make_float2(v.x, v.x);  dI[1] = make_float2(v.y, v.y);
        dI[2] = make_float2(v.z, v.z);  dI[3] = make_float2(v.w, v.w);
        dQ[0] = make_float2(qv.x, qv.x); dQ[1] = make_float2(qv.y, qv.y);
        dQ[2] = make_float2(qv.z, qv.z); dQ[3] = make_float2(qv.w, qv.w);
    }
    __syncthreads();

    // per-thread operand selection: 8 cols at c0
    const float2* Asrc;
    const float* Wbase;
    int wstride, c0;
    if (tc < 16)      { Asrc = sIVd; Wbase = sWE; wstride = VV; c0 = tc * 8; }
    else if (tc < 32) { Asrc = sIVd; Wbase = sWA; wstride = VV; c0 = (tc - 16) * 8; }
    else              { Asrc = sQKd; Wbase = sWK; wstride = CC; c0 = (tc - 32) * 8; }

    // acc[i][j]: row tr*8+i, cols (c0+2j, c0+2j+1)
    ull acc[8][4];
    if (tc < 16) {
        const float4 b0 = *(const float4*)(erase_b + c0);
        const float4 b1 = *(const float4*)(erase_b + c0 + 4);
#pragma unroll
        for (int i = 0; i < 8; i++) {
            acc[i][0] = pack2(b0.x, b0.y); acc[i][1] = pack2(b0.z, b0.w);
            acc[i][2] = pack2(b1.x, b1.y); acc[i][3] = pack2(b1.z, b1.w);
        }
    } else if (tc < 32) {
        const float4 b0 = *(const float4*)(add_b + c0);
        const float4 b1 = *(const float4*)(add_b + c0 + 4);
#pragma unroll
        for (int i = 0; i < 8; i++) {
            acc[i][0] = pack2(b0.x, b0.y); acc[i][1] = pack2(b0.z, b0.w);
            acc[i][2] = pack2(b1.x, b1.y); acc[i][3] = pack2(b1.z, b1.w);
        }
    } else {
        const ull z = pack2(0.f, 0.f);
#pragma unroll
        for (int i = 0; i < 8; i++)
            { acc[i][0] = z; acc[i][1] = z; acc[i][2] = z; acc[i][3] = z; }
    }

    const float2* Ath = Asrc + tr * 8 * KK;

    for (int ch = 0; ch < NKCH; ch++) {
        const int buf = ch & 1;
        mbar_wait(mb, ch & 1);
        __syncthreads();
        if (t == 0 && ch + 1 < NKCH) {
            const int nb = buf ^ 1, k0n = (ch + 1) * KCH;
            mbar_expect_tx(mb, WCH_TOT);
            bulk_g2s(smem_u32(sWE + nb * KCH * VV), erase_W    + k0n * VV, WCH_E, mb);
            bulk_g2s(smem_u32(sWA + nb * KCH * VV), add_W      + k0n * VV, WCH_E, mb);
            bulk_g2s(smem_u32(sWK + nb * KCH * CC), key_memory + k0n * CC, WCH_K, mb);
        }

        const float* W = Wbase + buf * KCH * wstride + c0;
        const float2* A = Ath + ch * KCH;
#pragma unroll
        for (int kk = 0; kk < KCH; kk += 2) {
            // W: 8 cols at k and k+1 -> 4 LDS.128 (each = 2 packed col-pairs)
            const ulonglong2 w0a = *(const ulonglong2*)(W + kk * wstride);
            const ulonglong2 w0b = *(const ulonglong2*)(W + kk * wstride + 4);
            const ulonglong2 w1a = *(const ulonglong2*)(W + (kk + 1) * wstride);
            const ulonglong2 w1b = *(const ulonglong2*)(W + (kk + 1) * wstride + 4);
#pragma unroll
            for (int i = 0; i < 8; i++) {
                // dup-pairs for k (lo) and k+1 (hi) of row i, one LDS.128
                const ulonglong2 ad = *(const ulonglong2*)(A + i * KK + kk);
                acc[i][0] = fma2(ad.x, w0a.x, acc[i][0]);
                acc[i][1] = fma2(ad.x, w0a.y, acc[i][1]);
                acc[i][2] = fma2(ad.x, w0b.x, acc[i][2]);
                acc[i][3] = fma2(ad.x, w0b.y, acc[i][3]);
                acc[i][0] = fma2(ad.y, w1a.x, acc[i][0]);
                acc[i][1] = fma2(ad.y, w1a.y, acc[i][1]);
                acc[i][2] = fma2(ad.y, w1b.x, acc[i][2]);
                acc[i][3] = fma2(ad.y, w1b.y, acc[i][3]);
            }
        }
    }

    // ---- Epilogue: 8 cols per thread = 2 float4 per row ----
    if (tc < 32) {
        const bool is_erase = (tc < 16);
        const int sl  = c0 >> 5;                       // 8 cols within one slice
        const int off = (is_erase ? 0 : 32) + (c0 & 31);
#pragma unroll
        for (int i = 0; i < 8; i++) {
            const int r = row0 + tr * 8 + i;
            const int b = r / SS, s = r - b * SS;
            float2 f0 = unpack2(acc[i][0]), f1 = unpack2(acc[i][1]);
            float2 f2 = unpack2(acc[i][2]), f3 = unpack2(acc[i][3]);
            float4 oa, ob;
            if (is_erase) {
                oa.x = -1.f / (1.f + __expf(-f0.x)); oa.y = -1.f / (1.f + __expf(-f0.y));
                oa.z = -1.f / (1.f + __expf(-f1.x)); oa.w = -1.f / (1.f + __expf(-f1.y));
                ob.x = -1.f / (1.f + __expf(-f2.x)); ob.y = -1.f / (1.f + __expf(-f2.y));
                ob.z = -1.f / (1.f + __expf(-f3.x)); ob.w = -1.f / (1.f + __expf(-f3.y));
            } else {
                oa.x = tanhf(f0.x); oa.y = tanhf(f0.y);
                oa.z = tanhf(f1.x); oa.w = tanhf(f1.y);
                ob.x = tanhf(f2.x); ob.y = tanhf(f2.y);
                ob.z = tanhf(f3.x); ob.w = tanhf(f3.y);
            }
            float* base = &g_slice[((size_t)(b * NSLICE + sl) * SS + s) * RECF + off];
            *(float4*)base = oa;
            *(float4*)(base + 4) = ob;
        }
    } else {
#pragma unroll
        for (int i = 0; i < 8; i++) {
            const int lr = tr * 8 + i;
            float2 f0 = unpack2(acc[i][0]), f1 = unpack2(acc[i][1]);
            float2 f2 = unpack2(acc[i][2]), f3 = unpack2(acc[i][3]);
            float4 oa, ob;
            oa.x = f0.x; oa.y = f0.y; oa.z = f1.x; oa.w = f1.y;
            ob.x = f2.x; ob.y = f2.y; ob.z = f3.x; ob.w = f3.y;
            *(float4*)&sLg[lr][c0 + 0] = oa;
            *(float4*)&sLg[lr][c0 + 4] = ob;
        }
    }
    __syncthreads();

    if (t < PROWS) {
        float mx = -1e30f;
#pragma unroll
        for (int c = 0; c < CC; c++) mx = fmaxf(mx, sLg[t][c]);
        float sum = 0.f;
#pragma unroll
        for (int c = 0; c < CC; c++) { float e = __expf(sLg[t][c] - mx); sLg[t][c] = e; sum += e; }
        const float inv = 1.f / sum;
#pragma unroll
        for (int c = 0; c < CC; c++) sLg[t][c] *= inv;
    }
    __syncthreads();

    for (int idx = t; idx < PROWS * (CC / 4); idx += PT) {
        const int r = idx >> 4, q = idx & 15;
        const int gr = row0 + r;
        const int b = gr / SS, s = gr - b * SS;
        const float4 o = *(const float4*)&sLg[r][q * 4];
#pragma unroll
        for (int j = 0; j < NSLICE; j++)
            *(float4*)&g_slice[((size_t)(b * NSLICE + j) * SS + s) * RECF + 64 + q * 4] = o;
    }
}

// ---------------------------------------------------------------------------
// Kernel B: sliced scan (UNCHANGED from passing R10).
// ---------------------------------------------------------------------------
__global__ __launch_bounds__(256) void scan_kernel(
    const float* __restrict__ init_value_memory)
{
    extern __shared__ __align__(16) float dsm[];

    const int bs = blockIdx.x;
    const int sl = bs & 3;
    const int b  = bs >> 2;
    const int t  = threadIdx.x;
    const int pg = t >> 4;
    const int cg = t & 15;

    {
        const float4* src = (const float4*)(g_slice + (size_t)bs * SS * RECF);
        float4* dst = (float4*)dsm;
#pragma unroll
        for (int i = 0; i < 25; i++)
            dst[t + i * 256] = src[t + i * 256];
    }

    const int v0 = sl * SLICEV + pg * 2;
    ull m2[4];
    {
        const float4 ra = *(const float4*)(init_value_memory + (v0    ) * CC + cg * 4);
        const float4 rb = *(const float4*)(init_value_memory + (v0 + 1) * CC + cg * 4);
        m2[0] = pack2(ra.x, rb.x);
        m2[1] = pack2(ra.y, rb.y);
        m2[2] = pack2(ra.z, rb.z);
        m2[3] = pack2(ra.w, rb.w);
    }
    __syncthreads();

    const float* sp = dsm;
#pragma unroll 4
    for (int s = 0; s < SS; s++, sp += RECF) {
        const ull ne = *(const ull*)(sp + pg * 2);
        const ull aa = *(const ull*)(sp + 32 + pg * 2);
        const float4 wf = *(const float4*)(sp + 64 + cg * 4);
        const ull w0 = pack2(wf.x, wf.x);
        const ull w1 = pack2(wf.y, wf.y);
        const ull w2 = pack2(wf.z, wf.z);
        const ull w3 = pack2(wf.w, wf.w);
        m2[0] = fma2(w0, fma2(m2[0], ne, aa), m2[0]);
        m2[1] = fma2(w1, fma2(m2[1], ne, aa), m2[1]);
        m2[2] = fma2(w2, fma2(m2[2], ne, aa), m2[2]);
        m2[3] = fma2(w3, fma2(m2[3], ne, aa), m2[3]);
    }

    float* dst0 = g_mem + ((size_t)b * VV + v0) * CC + cg * 4;
    float* dst1 = dst0 + CC;
    float2 f0 = unpack2(m2[0]), f1 = unpack2(m2[1]), f2 = unpack2(m2[2]), f3 = unpack2(m2[3]);
    float4 oa; oa.x = f0.x; oa.y = f1.x; oa.z = f2.x; oa.w = f3.x;
    float4 ob; ob.x = f0.y; ob.y = f1.y; ob.z = f2.y; ob.w = f3.y;
    *(float4*)dst0 = oa;
    *(float4*)dst1 = ob;
}

// ---------------------------------------------------------------------------
// Kernel C: readout (UNCHANGED from passing R10).
// ---------------------------------------------------------------------------
__global__ __launch_bounds__(256) void readout_kernel(
    const float* __restrict__ q_emb,
    const float* __restrict__ key_memory,
    const float* __restrict__ summ_W,
    const float* __restrict__ summ_b,
    const float* __restrict__ out_W,
    const float* __restrict__ out_b,
    const int*   __restrict__ target_id,
    float* __restrict__ out)
{
    __shared__ float sMem[VV][CC + 1];
    __shared__ float sQv[KK];
    __shared__ float sWt[CC];
    __shared__ float sCat[VV + KK];
    __shared__ float sPart[4][CC + 1];
    __shared__ float sRed[8][SUMD + 4];
    __shared__ float sRed2[4];

    const int b    = blockIdx.x;
    const int t    = threadIdx.x;
    const int lane = t & 31;
    const int wid  = t >> 5;

    const float* gm = g_mem + (size_t)b * VV * CC;
#pragma unroll
    for (int i = 0; i < 8; i++) {
        const int idx = t + i * 256;
        const int v = idx >> 4, q = idx & 15;
        const float4 val = *(const float4*)(gm + v * CC + q * 4);
        sMem[v][q * 4 + 0] = val.x;
        sMem[v][q * 4 + 1] = val.y;
        sMem[v][q * 4 + 2] = val.z;
        sMem[v][q * 4 + 3] = val.w;
    }
    if (t < KK) sQv[t] = q_emb[(size_t)target_id[b] * KK + t];
    __syncthreads();

    {
        const int c = t & 63, kg = t >> 6;
        float acc = 0.f;
#pragma unroll
        for (int j = 0; j < 32; j++)
            acc = fmaf(sQv[kg * 32 + j], __ldg(key_memory + (kg * 32 + j) * CC + c), acc);
        sPart[kg][c] = acc;
    }
    __syncthreads();
    if (t < CC) {
        float s = 0.f;
#pragma unroll
        for (int j = 0; j < 4; j++) s += sPart[j][t];
        sWt[t] = s;
    }
    __syncthreads();
    if (t < 32) {
        float l0 = sWt[t], l1 = sWt[t + 32];
        float mx = fmaxf(l0, l1);
#pragma unroll
        for (int off = 16; off > 0; off >>= 1)
            mx = fmaxf(mx, __shfl_xor_sync(0xffffffffu, mx, off));
        float e0 = __expf(l0 - mx), e1 = __expf(l1 - mx);
        float sm = e0 + e1;
#pragma unroll
        for (int off = 16; off > 0; off >>= 1)
            sm += __shfl_xor_sync(0xffffffffu, sm, off);
        const float inv = 1.f / sm;
        sWt[t] = e0 * inv;
        sWt[t + 32] = e1 * inv;
    }
    __syncthreads();

    if (t < VV) {
        float acc = 0.f;
#pragma unroll
        for (int c = 0; c < CC; c++)
            acc = fmaf(sMem[t][c], sWt[c], acc);
        sCat[t] = acc;
    } else {
        sCat[t] = sQv[t - 128];
    }
    __syncthreads();

    {
        float4 acc4 = make_float4(0.f, 0.f, 0.f, 0.f);
#pragma unroll
        for (int j = 0; j < 32; j++) {
            const int row = wid * 32 + j;
            const float x = sCat[row];
            const float4 wr = *(const float4*)(summ_W + row * SUMD + lane * 4);
            acc4.x = fmaf(x, wr.x, acc4.x);
            acc4.y = fmaf(x, wr.y, acc4.y);
            acc4.z = fmaf(x, wr.z, acc4.z);
            acc4.w = fmaf(x, wr.w, acc4.w);
        }
        *(float4*)&sRed[wid][lane * 4] = acc4;
    }
    __syncthreads();

    if (t < SUMD) {
        float s = 0.f;
#pragma unroll
        for (int j = 0; j < 8; j++) s += sRed[j][t];
        const float sm = tanhf(s + summ_b[t]);
        float p = sm * __ldg(out_W + t);
#pragma unroll
        for (int off = 16; off > 0; off >>= 1)
            p += __shfl_down_sync(0xffffffffu, p, off);
        if (lane == 0) sRed2[wid] = p;
    }
    __syncthreads();
    if (t == 0)
        out[b] = sRed2[0] + sRed2[1] + sRed2[2] + sRed2[3] + out_b[0];
}

// ---------------------------------------------------------------------------
extern "C" void kernel_launch(void* const* d_in, const int* in_sizes, int n_in,
                              void* d_out, int out_size)
{
    const float* q_emb      = (const float*)d_in[0];
    const float* i_emb      = (const float*)d_in[1];
    const float* key_memory = (const float*)d_in[2];
    const float* init_vm    = (const float*)d_in[3];
    const float* erase_W    = (const float*)d_in[4];
    const float* erase_b    = (const float*)d_in[5];
    const float* add_W      = (const float*)d_in[6];
    const float* add_b      = (const float*)d_in[7];
    const float* summ_W     = (const float*)d_in[8];
    const float* summ_b     = (const float*)d_in[9];
    const float* out_W      = (const float*)d_in[10];
    const float* out_b      = (const float*)d_in[11];
    const int*   input      = (const int*)d_in[12];
    const int*   target_id  = (const int*)d_in[13];
    float* out = (float*)d_out;

    cudaFuncSetAttribute(precompute_kernel, cudaFuncAttributeMaxDynamicSharedMemorySize, PRE_SMEM);
    cudaFuncSetAttribute(scan_kernel, cudaFuncAttributeMaxDynamicSharedMemorySize, SCAN_SMEM);

    precompute_kernel<<<NROWS / PROWS, PT, PRE_SMEM>>>(
        q_emb, i_emb, key_memory, erase_W, erase_b, add_W, add_b, input);

    scan_kernel<<<BB * NSLICE, 256, SCAN_SMEM>>>(init_vm);

    readout_kernel<<<BB, 256>>>(
        q_emb, key_memory, summ_W, summ_b, out_W, out_b, target_id, out);
}